// round 6
// baseline (speedup 1.0000x reference)
#include <cuda_runtime.h>

#define HH    640
#define WW    640
#define BATCH 4
#define NLAB  10
#define NPIX  (HH*WW)
#define TILE_W 128
#define TILE_H 8
#define GXB (WW/TILE_W)              // 5
#define GYB (HH/TILE_H)              // 80
#define NBLOCKS (GXB*(GYB+1)*BATCH)  // 1620 (includes edge blocks)
#define SMW 136                      // smem row width (floats): left halo 4, 128 center, right halo 1 (+pad)

__device__ float d_accIn[BATCH];
__device__ float d_accGrad[BATCH];
__device__ float d_boxF[BATCH*NLAB];
__device__ float d_boxE[BATCH*NLAB];
__device__ unsigned d_count;

__device__ __forceinline__ float wsum(float v) {
    #pragma unroll
    for (int o = 16; o; o >>= 1) v += __shfl_down_sync(0xffffffffu, v, o);
    return v;
}

struct G4 { float gx[4], gy[4], c[4]; };

// Separable sobel for a 1x4 strip. Center pixel k lives at smem col 4*tx+4+k.
// p[-1] via LDS.64 at col 4tx+2 (.y), p0..p3 via LDS.128 at 4tx+4, p4 via LDS.64 at 4tx+8 (.x).
__device__ __forceinline__ G4 sobel4(const float sm[TILE_H+2][SMW], int ty, int tx) {
    G4 o;
    float t1[3][4], t2[3][4];
    #pragma unroll
    for (int r = 0; r < 3; r++) {
        const float* row = &sm[ty + r][0];
        float2 L = *reinterpret_cast<const float2*>(row + 4*tx + 2);
        float4 M = *reinterpret_cast<const float4*>(row + 4*tx + 4);
        float2 R = *reinterpret_cast<const float2*>(row + 4*tx + 8);
        float pm1 = L.y, p0 = M.x, p1 = M.y, p2 = M.z, p3 = M.w, p4 = R.x;
        t1[r][0] = pm1 + 2.f*p0 + p1;  t1[r][1] = p0 + 2.f*p1 + p2;
        t1[r][2] = p1 + 2.f*p2 + p3;   t1[r][3] = p2 + 2.f*p3 + p4;
        t2[r][0] = p1 - pm1;  t2[r][1] = p2 - p0;  t2[r][2] = p3 - p1;  t2[r][3] = p4 - p2;
        if (r == 1) { o.c[0] = p0; o.c[1] = p1; o.c[2] = p2; o.c[3] = p3; }
    }
    #pragma unroll
    for (int k = 0; k < 4; k++) {
        o.gx[k] = t2[0][k] + 2.f*t2[1][k] + t2[2][k];
        o.gy[k] = t1[0][k] - t1[2][k];
    }
    return o;
}

// Full masked 3x3 sobel F at (r,c) from global memory (ring pixels; L2/L1-resident).
__device__ float maskedF_g(const float* __restrict__ vis, const float* __restrict__ th,
                           const float* __restrict__ gen, int base, int r, int c, int4 B)
{
    float v[8], t[8], g[8];
    const int dr[8] = {-1,-1,-1, 0, 0, 1, 1, 1};
    const int dc[8] = {-1, 0, 1,-1, 1,-1, 0, 1};
    #pragma unroll
    for (int i = 0; i < 8; i++) {
        int rr = r + dr[i], cc = c + dc[i];
        bool in = (rr >= B.y) & (rr < B.w) & (cc >= B.x) & (cc < B.z);
        int q = in ? base + rr * WW + cc : base;
        float m = in ? 1.f : 0.f;
        v[i] = vis[q] * m; t[i] = th[q] * m; g[i] = gen[q] * m;
    }
    float gxV = (v[2]-v[0]) + 2.f*(v[4]-v[3]) + (v[7]-v[5]);
    float gyV = (v[0]-v[5]) + 2.f*(v[1]-v[6]) + (v[2]-v[7]);
    float gxT = (t[2]-t[0]) + 2.f*(t[4]-t[3]) + (t[7]-t[5]);
    float gyT = (t[0]-t[5]) + 2.f*(t[1]-t[6]) + (t[2]-t[7]);
    float gxG = (g[2]-g[0]) + 2.f*(g[4]-g[3]) + (g[7]-g[5]);
    float gyG = (g[0]-g[5]) + 2.f*(g[1]-g[6]) + (g[2]-g[7]);
    float gradV = fabsf(gxV) + fabsf(gyV);
    float g7 = fabsf(0.3f*gxV + 0.7f*gxT) + fabsf(0.3f*gyV + 0.7f*gyT);
    float gradG = fabsf(gxG) + fabsf(gyG);
    return fabsf(gradG - fmaxf(gradV, g7));
}

__global__ __launch_bounds__(256) void fused_k(
    const float* __restrict__ vis, const float* __restrict__ th,
    const float* __restrict__ gen, const int* __restrict__ label,
    const float* __restrict__ bptr, const float* __restrict__ cptr,
    float* __restrict__ out)
{
    __shared__ float sV[TILE_H+2][SMW], sT[TILE_H+2][SMW], sG[TILE_H+2][SMW];
    __shared__ int4  sBox[NLAB];
    __shared__ int   sBoxIdx[NLAB];
    __shared__ int   sN;
    __shared__ int   sIsLast;
    __shared__ float sLs[BATCH*NLAB], sL1[BATCH*NLAB];

    const int tx = threadIdx.x, ty = threadIdx.y;
    const int tid = ty * 32 + tx;
    const int bz = blockIdx.z;
    const int base = bz * NPIX;

    if (blockIdx.y < GYB) {
        // ================= main stencil path =================
        const int colStart = blockIdx.x * TILE_W;
        const int rowStart = blockIdx.y * TILE_H;

        if (tid == 0) sN = 0;

        // Halo load: 34 aligned float4 per row, (TILE_H+2) rows, 3 arrays.
        // gc0 = colStart-4+4j is always a multiple of 4 -> each float4 fully in or fully out.
        for (int i = tid; i < (TILE_H+2) * 34; i += 256) {
            int lr = i / 34, j = i - lr * 34;
            int gr = rowStart - 1 + lr;
            int gc0 = colStart - 4 + 4 * j;
            bool in = (gr >= 0) & (gr < HH) & (gc0 >= 0) & (gc0 < WW);
            float4 fv = make_float4(0.f,0.f,0.f,0.f), ft = fv, fg = fv;
            if (in) {
                int q = base + gr * WW + gc0;
                fv = *reinterpret_cast<const float4*>(vis + q);
                ft = *reinterpret_cast<const float4*>(th  + q);
                fg = *reinterpret_cast<const float4*>(gen + q);
            }
            *reinterpret_cast<float4*>(&sV[lr][4*j]) = fv;
            *reinterpret_cast<float4*>(&sT[lr][4*j]) = ft;
            *reinterpret_cast<float4*>(&sG[lr][4*j]) = fg;
        }
        __syncthreads();

        if (tid < NLAB) {
            const int* L = label + (bz * NLAB + tid) * 5;
            int x1 = L[1], y1 = L[2], x2 = L[3], y2 = L[4];
            if (x2 > x1 && y2 > y1 &&
                x1 < colStart + TILE_W && x2 > colStart &&
                y1 < rowStart + TILE_H && y2 > rowStart) {
                int p = atomicAdd(&sN, 1);
                sBox[p] = make_int4(x1, y1, x2, y2);
                sBoxIdx[p] = bz * NLAB + tid;
            }
        }
        __syncthreads();
        const int nOv = sN;

        G4 gv = sobel4(sV, ty, tx);
        G4 gt = sobel4(sT, ty, tx);
        G4 gg = sobel4(sG, ty, tx);

        float F[4], E[4];
        float li = 0.f, lg = 0.f;
        #pragma unroll
        for (int k = 0; k < 4; k++) {
            float gradV = fabsf(gv.gx[k]) + fabsf(gv.gy[k]);
            float gradG = fabsf(gg.gx[k]) + fabsf(gg.gy[k]);
            float g5 = fabsf(0.5f*(gv.gx[k] + gt.gx[k])) + fabsf(0.5f*(gv.gy[k] + gt.gy[k]));
            float g7 = fabsf(0.3f*gv.gx[k] + 0.7f*gt.gx[k]) + fabsf(0.3f*gv.gy[k] + 0.7f*gt.gy[k]);
            float xm  = 0.5f * (gv.c[k] + gt.c[k]);
            float xm7 = 0.3f * gv.c[k] + 0.7f * gt.c[k];
            li  += fabsf(gg.c[k] - fmaxf(gv.c[k], xm));
            lg  += fabsf(gradG - fmaxf(gradV, g5));
            F[k] = fabsf(gradG - fmaxf(gradV, g7));
            E[k] = fabsf(gg.c[k] - fmaxf(gv.c[k], xm7));
        }

        // Per-box: E over full box, F over strict interior only (ring -> edge blocks).
        const int r = rowStart + ty;
        const int cb = colStart + tx * 4;
        for (int b = 0; b < nOv; b++) {
            int4 B = sBox[b];
            float fb = 0.f, eb = 0.f;
            if (r >= B.y && r < B.w) {
                bool rowInt = (r > B.y) & (r < B.w - 1);
                #pragma unroll
                for (int k = 0; k < 4; k++) {
                    int c = cb + k;
                    bool inB = (c >= B.x) & (c < B.z);
                    if (inB) eb += E[k];
                    if (inB & rowInt & (c > B.x) & (c < B.z - 1)) fb += F[k];
                }
            }
            fb = wsum(fb); eb = wsum(eb);
            if (tx == 0) {
                atomicAdd(&d_boxF[sBoxIdx[b]], fb);
                atomicAdd(&d_boxE[sBoxIdx[b]], eb);
            }
        }

        li = wsum(li); lg = wsum(lg);
        if (tx == 0) {
            atomicAdd(&d_accIn[bz], li);
            atomicAdd(&d_accGrad[bz], lg);
        }
    } else {
        // ================= box ring pass (exact masked sobel) =================
        const int warpG = blockIdx.x * 8 + ty;   // 0..39
        const int b = warpG >> 2;                // box 0..9
        const int q = warpG & 3;
        const int* L = label + (bz * NLAB + b) * 5;
        int4 B = make_int4(L[1], L[2], L[3], L[4]);
        int w = B.z - B.x, h = B.w - B.y;
        if (w > 0 && h > 0) {
            int topN  = w;
            int botN  = (h > 1) ? w : 0;
            int sideH = (h > 2) ? h - 2 : 0;
            int leftN = sideH;
            int rightN = (w > 1) ? sideH : 0;
            int Ltot = topN + botN + leftN + rightN;
            float sF = 0.f;
            for (int idx = q * 32 + tx; idx < Ltot; idx += 128) {
                int t = idx, r, c;
                if (t < topN) { r = B.y; c = B.x + t; }
                else { t -= topN;
                    if (t < botN) { r = B.w - 1; c = B.x + t; }
                    else { t -= botN;
                        if (t < leftN) { r = B.y + 1 + t; c = B.x; }
                        else { t -= leftN; r = B.y + 1 + t; c = B.z - 1; }
                    }
                }
                sF += maskedF_g(vis, th, gen, base, r, c, B);
            }
            sF = wsum(sF);
            if (tx == 0) atomicAdd(&d_boxF[bz * NLAB + b], sF);
        }
    }

    // ================= last-block finalize =================
    __threadfence();
    __syncthreads();
    if (tid == 0) {
        unsigned o = atomicAdd(&d_count, 1u);
        sIsLast = (o == NBLOCKS - 1);
    }
    __syncthreads();
    if (!sIsLast) return;

    if (tid < BATCH * NLAB) {
        const int* L = label + tid * 5;
        int x1 = L[1], y1 = L[2], x2 = L[3], y2 = L[4];
        bool valid = !(x1 == 0 && y1 == 0 && x2 == 0 && y2 == 0);
        float area = (float)((y2 - y1) * (x2 - x1));   // C == 1
        float sa = fmaxf(area, 1.f);
        volatile float* vF = (volatile float*)d_boxF;
        volatile float* vE = (volatile float*)d_boxE;
        float f = vF[tid], e = vE[tid];
        float vv = valid ? 1.f : 0.f;
        sLs[tid] = (f / sa) * vv;
        sL1[tid] = (e / sa) * vv;
        d_boxF[tid] = 0.f; d_boxE[tid] = 0.f;          // reset for next replay
    }
    __syncthreads();
    if (tid < BATCH) {
        volatile float* aI = (volatile float*)d_accIn;
        volatile float* aG = (volatile float*)d_accGrad;
        const float inv = 1.0f / (float)NPIX;          // C == 1
        float loss_in   = aI[tid] * inv;
        float loss_grad = aG[tid] * inv;
        d_accIn[tid] = 0.f; d_accGrad[tid] = 0.f;

        float sLsum = 0.f, s1sum = 0.f, cnt = 0.f;
        for (int n = 0; n < NLAB; n++) {
            float a = sLs[tid * NLAB + n], bb = sL1[tid * NLAB + n];
            sLsum += a; s1sum += bb;
            if (a != 0.f || bb != 0.f) cnt += 1.f;
        }
        float safe_cnt = fmaxf(cnt, 1.f);
        float ls  = (cnt > 0.f) ? sLsum / safe_cnt : 0.f;
        float lin = (cnt > 0.f) ? s1sum / safe_cnt : 0.f;
        float alpha = *bptr, beta = *cptr;
        out[0*BATCH + tid] = 0.f;
        out[1*BATCH + tid] = alpha * loss_in + (1.f - alpha) * loss_grad;
        out[2*BATCH + tid] = (1.f - beta) * ls + beta * lin;
        out[3*BATCH + tid] = loss_in;
        out[4*BATCH + tid] = loss_grad;
        out[5*BATCH + tid] = ls;
        out[6*BATCH + tid] = lin;
    }
    if (tid == 0) d_count = 0;
}

extern "C" void kernel_launch(void* const* d_in, const int* in_sizes, int n_in,
                              void* d_out, int out_size)
{
    (void)in_sizes; (void)n_in; (void)out_size;
    const float* bptr  = (const float*)d_in[0];
    const float* cptr  = (const float*)d_in[1];
    const float* vis   = (const float*)d_in[2];
    // d_in[3] = image_ir (unused by the reference)
    const float* gen   = (const float*)d_in[4];
    const int*   label = (const int*)d_in[5];
    const float* th    = (const float*)d_in[6];
    float* out = (float*)d_out;

    dim3 grid(GXB, GYB + 1, BATCH);
    dim3 blk(32, 8);
    fused_k<<<grid, blk>>>(vis, th, gen, label, bptr, cptr, out);
}

// round 7
// speedup vs baseline: 1.7369x; 1.7369x over previous
#include <cuda_runtime.h>

#define HH    640
#define WW    640
#define BATCH 4
#define NLAB  10
#define NPIX  (HH*WW)
#define TILE_W 128
#define TILE_H 8
#define GXB (WW/TILE_W)            // 5
#define GYB (HH/TILE_H)            // 80
#define NBLOCKS (GXB*GYB*BATCH)    // 1600

// Persistent accumulators (zero-initialized at load; kernel restores zeros each call)
__device__ float d_accIn[BATCH];
__device__ float d_accGrad[BATCH];
__device__ float d_boxF[BATCH*NLAB];
__device__ float d_boxE[BATCH*NLAB];
__device__ unsigned d_count;

__device__ __forceinline__ float wsum(float v) {
    #pragma unroll
    for (int o = 16; o; o >>= 1) v += __shfl_down_sync(0xffffffffu, v, o);
    return v;
}

struct G4 { float gx[4], gy[4], c[4]; };

// Separable sobel for a 1x4 output strip from a shared tile.
__device__ __forceinline__ G4 sobel4(const float sm[10][132], int ty, int lc0) {
    G4 o;
    float t1[3][4], t2[3][4];
    #pragma unroll
    for (int r = 0; r < 3; r++) {
        const float* row = &sm[ty + r][lc0];
        float4 a = *reinterpret_cast<const float4*>(row);
        float2 b = *reinterpret_cast<const float2*>(row + 4);
        float v0=a.x, v1=a.y, v2=a.z, v3=a.w, v4=b.x, v5=b.y;
        t1[r][0]=v0+2.f*v1+v2; t1[r][1]=v1+2.f*v2+v3;
        t1[r][2]=v2+2.f*v3+v4; t1[r][3]=v3+2.f*v4+v5;
        t2[r][0]=v2-v0; t2[r][1]=v3-v1; t2[r][2]=v4-v2; t2[r][3]=v5-v3;
        if (r == 1) { o.c[0]=v1; o.c[1]=v2; o.c[2]=v3; o.c[3]=v4; }
    }
    #pragma unroll
    for (int k = 0; k < 4; k++) {
        o.gx[k] = t2[0][k] + 2.f*t2[1][k] + t2[2][k];
        o.gy[k] = t1[0][k] - t1[2][k];
    }
    return o;
}

// Exact masked sobel F at a ring pixel, using the shared tiles (halo covers ±1).
__device__ float maskedF(const float sV[10][132], const float sT[10][132],
                         const float sG[10][132], int ty, int lcc,
                         int r, int c, int4 B)
{
    const float wx[3][3] = {{-1,0,1},{-2,0,2},{-1,0,1}};
    const float wy[3][3] = {{1,2,1},{0,0,0},{-1,-2,-1}};
    float gxV=0,gyV=0,gxT=0,gyT=0,gxG=0,gyG=0;
    #pragma unroll
    for (int dr = 0; dr < 3; dr++)
    #pragma unroll
    for (int dc = 0; dc < 3; dc++) {
        int rr = r + dr - 1, cc = c + dc - 1;
        bool in = (rr >= B.y) & (rr < B.w) & (cc >= B.x) & (cc < B.z);
        float m = in ? 1.f : 0.f;
        float fv = sV[ty + dr][lcc - 1 + dc] * m;
        float ft = sT[ty + dr][lcc - 1 + dc] * m;
        float fg = sG[ty + dr][lcc - 1 + dc] * m;
        gxV += wx[dr][dc] * fv; gyV += wy[dr][dc] * fv;
        gxT += wx[dr][dc] * ft; gyT += wy[dr][dc] * ft;
        gxG += wx[dr][dc] * fg; gyG += wy[dr][dc] * fg;
    }
    float gradV = fabsf(gxV) + fabsf(gyV);
    float grad7 = fabsf(0.3f*gxV + 0.7f*gxT) + fabsf(0.3f*gyV + 0.7f*gyT);
    float gradG = fabsf(gxG) + fabsf(gyG);
    return fabsf(gradG - fmaxf(gradV, grad7));
}

__global__ __launch_bounds__(256, 5) void fused_k(
    const float* __restrict__ vis, const float* __restrict__ th,
    const float* __restrict__ gen, const int* __restrict__ label,
    const float* __restrict__ bptr, const float* __restrict__ cptr,
    float* __restrict__ out)
{
    __shared__ float sV[10][132], sT[10][132], sG[10][132];
    __shared__ int4  sBox[NLAB];
    __shared__ int   sBoxIdx[NLAB];
    __shared__ float sAF[NLAB], sAE[NLAB];
    __shared__ int   sN;
    __shared__ float redIn[8], redGr[8];
    __shared__ int   sIsLast;
    __shared__ float sLs[BATCH*NLAB], sL1[BATCH*NLAB];

    const int tx = threadIdx.x, ty = threadIdx.y;
    const int tid = ty * 32 + tx;
    const int bz = blockIdx.z;
    const int colStart = blockIdx.x * TILE_W;
    const int rowStart = blockIdx.y * TILE_H;
    const int base = bz * NPIX;

    // Warp 0: init + build overlapping-box list (no extra block barrier needed)
    if (tid < 32) {
        if (tid == 0) sN = 0;
        if (tid < NLAB) { sAF[tid] = 0.f; sAE[tid] = 0.f; }
        __syncwarp();
        if (tid < NLAB) {
            const int* L = label + (bz * NLAB + tid) * 5;
            int x1 = L[1], y1 = L[2], x2 = L[3], y2 = L[4];
            if (x2 > x1 && y2 > y1 &&
                x1 < colStart + TILE_W && x2 > colStart &&
                y1 < rowStart + TILE_H && y2 > rowStart) {
                int p = atomicAdd(&sN, 1);
                sBox[p] = make_int4(x1, y1, x2, y2);
                sBoxIdx[p] = bz * NLAB + tid;
            }
        }
    }

    // Load 10x130 halo tiles of the 3 images
    for (int i = tid; i < 10 * 130; i += 256) {
        int lr = i / 130, lc = i - lr * 130;
        int gr = rowStart - 1 + lr, gc = colStart - 1 + lc;
        bool in = (gr >= 0) & (gr < HH) & (gc >= 0) & (gc < WW);
        int q = in ? base + gr * WW + gc : base;
        float fv = in ? vis[q] : 0.f;
        float ft = in ? th[q]  : 0.f;
        float fg = in ? gen[q] : 0.f;
        sV[lr][lc] = fv; sT[lr][lc] = ft; sG[lr][lc] = fg;
    }
    __syncthreads();
    const int nOv = sN;

    // Stencils
    const int lc0 = tx * 4;
    G4 gv = sobel4(sV, ty, lc0);
    G4 gt = sobel4(sT, ty, lc0);
    G4 gg = sobel4(sG, ty, lc0);

    float li = 0.f, lg = 0.f;
    #pragma unroll
    for (int k = 0; k < 4; k++) {
        float gradV = fabsf(gv.gx[k]) + fabsf(gv.gy[k]);
        float gradG = fabsf(gg.gx[k]) + fabsf(gg.gy[k]);
        float g5 = 0.5f * (fabsf(gv.gx[k] + gt.gx[k]) + fabsf(gv.gy[k] + gt.gy[k]));
        float xm = 0.5f * (gv.c[k] + gt.c[k]);
        li += fabsf(gg.c[k] - fmaxf(gv.c[k], xm));
        lg += fabsf(gradG - fmaxf(gradV, g5));
    }

    // Per-box accumulation (only when a box overlaps this tile)
    if (nOv > 0) {
        float F[4], E[4];
        #pragma unroll
        for (int k = 0; k < 4; k++) {
            float gradV = fabsf(gv.gx[k]) + fabsf(gv.gy[k]);
            float gradG = fabsf(gg.gx[k]) + fabsf(gg.gy[k]);
            float g7 = fabsf(0.3f*gv.gx[k] + 0.7f*gt.gx[k]) + fabsf(0.3f*gv.gy[k] + 0.7f*gt.gy[k]);
            float xm7 = 0.3f * gv.c[k] + 0.7f * gt.c[k];
            F[k] = fabsf(gradG - fmaxf(gradV, g7));
            E[k] = fabsf(gg.c[k] - fmaxf(gv.c[k], xm7));
        }
        const int r = rowStart + ty;
        const int cbase = colStart + tx * 4;
        for (int b = 0; b < nOv; b++) {
            int4 B = sBox[b];
            float fb = 0.f, eb = 0.f;
            bool rowIn = (r >= B.y) & (r < B.w);
            if (rowIn) {
                bool rowInt = (r > B.y) & (r < B.w - 1);
                #pragma unroll
                for (int k = 0; k < 4; k++) {
                    int c = cbase + k;
                    if (c >= B.x && c < B.z) {
                        eb += E[k];
                        if (rowInt && c > B.x && c < B.z - 1) fb += F[k];
                        else fb += maskedF(sV, sT, sG, ty, lc0 + k + 1, r, c, B);
                    }
                }
            }
            fb = wsum(fb); eb = wsum(eb);
            if ((tid & 31) == 0) { atomicAdd(&sAF[b], fb); atomicAdd(&sAE[b], eb); }
        }
    }

    // Block-staged reduce for li/lg (ONE global atomic per block per counter)
    li = wsum(li); lg = wsum(lg);
    if ((tid & 31) == 0) { redIn[tid >> 5] = li; redGr[tid >> 5] = lg; }
    __syncthreads();
    if (tid == 0) {
        float a = 0.f, bb = 0.f;
        #pragma unroll
        for (int i = 0; i < 8; i++) { a += redIn[i]; bb += redGr[i]; }
        atomicAdd(&d_accIn[bz],  a);
        atomicAdd(&d_accGrad[bz], bb);
    }
    if (tid < nOv) {
        atomicAdd(&d_boxF[sBoxIdx[tid]], sAF[tid]);
        atomicAdd(&d_boxE[sBoxIdx[tid]], sAE[tid]);
    }

    // Last-block finalize
    __threadfence();
    __syncthreads();
    if (tid == 0) {
        unsigned o = atomicAdd(&d_count, 1u);
        sIsLast = (o == NBLOCKS - 1);
    }
    __syncthreads();
    if (!sIsLast) return;

    if (tid < BATCH * NLAB) {
        const int* L = label + tid * 5;
        int x1 = L[1], y1 = L[2], x2 = L[3], y2 = L[4];
        bool valid = !(x1 == 0 && y1 == 0 && x2 == 0 && y2 == 0);
        float area = (float)((y2 - y1) * (x2 - x1));       // C == 1
        float sa = fmaxf(area, 1.f);
        volatile float* vF = (volatile float*)d_boxF;
        volatile float* vE = (volatile float*)d_boxE;
        float f = vF[tid], e = vE[tid];
        float vv = valid ? 1.f : 0.f;
        sLs[tid] = (f / sa) * vv;
        sL1[tid] = (e / sa) * vv;
        d_boxF[tid] = 0.f; d_boxE[tid] = 0.f;              // reset for next replay
    }
    __syncthreads();
    if (tid < BATCH) {
        volatile float* aI = (volatile float*)d_accIn;
        volatile float* aG = (volatile float*)d_accGrad;
        const float inv = 1.0f / (float)NPIX;              // C == 1
        float loss_in   = aI[tid] * inv;
        float loss_grad = aG[tid] * inv;
        d_accIn[tid] = 0.f; d_accGrad[tid] = 0.f;          // reset

        float sLsum = 0.f, s1sum = 0.f, cnt = 0.f;
        for (int n = 0; n < NLAB; n++) {
            float a = sLs[tid * NLAB + n], bb = sL1[tid * NLAB + n];
            sLsum += a; s1sum += bb;
            if (a != 0.f || bb != 0.f) cnt += 1.f;
        }
        float safe_cnt = fmaxf(cnt, 1.f);
        float ls  = (cnt > 0.f) ? sLsum / safe_cnt : 0.f;
        float lin = (cnt > 0.f) ? s1sum / safe_cnt : 0.f;
        float alpha = *bptr, beta = *cptr;
        out[0*BATCH + tid] = 0.f;                                         // loss_ss
        out[1*BATCH + tid] = alpha * loss_in + (1.f - alpha) * loss_grad; // loss_global
        out[2*BATCH + tid] = (1.f - beta) * ls + beta * lin;              // loss_label
        out[3*BATCH + tid] = loss_in;
        out[4*BATCH + tid] = loss_grad;
        out[5*BATCH + tid] = ls;
        out[6*BATCH + tid] = lin;
    }
    if (tid == 0) d_count = 0;                                            // reset
}

extern "C" void kernel_launch(void* const* d_in, const int* in_sizes, int n_in,
                              void* d_out, int out_size)
{
    (void)in_sizes; (void)n_in; (void)out_size;
    const float* bptr  = (const float*)d_in[0];
    const float* cptr  = (const float*)d_in[1];
    const float* vis   = (const float*)d_in[2];
    // d_in[3] = image_ir (unused by the reference)
    const float* gen   = (const float*)d_in[4];
    const int*   label = (const int*)d_in[5];
    const float* th    = (const float*)d_in[6];
    float* out = (float*)d_out;

    dim3 grid(GXB, GYB, BATCH);
    dim3 blk(32, 8);
    fused_k<<<grid, blk>>>(vis, th, gen, label, bptr, cptr, out);
}